// round 1
// baseline (speedup 1.0000x reference)
#include <cuda_runtime.h>
#include <math.h>

// ---------------------------------------------------------------------------
// Problem constants (fixed by the reference)
// ---------------------------------------------------------------------------
#define T_TOK 16384          // B*S = 8*2048
#define DLAT  1024
#define NEXP  4
#define RLORA 16
#define NLAYER 3

// ---------------------------------------------------------------------------
// Scratch (device globals: allocation-free rule)
// ---------------------------------------------------------------------------
__device__ float g_bufS[T_TOK * DLAT];        // 64 MB  - gated state s
__device__ float g_bufY[T_TOK * DLAT];        // 64 MB  - pre-LN y
__device__ float g_bufX[T_TOK * DLAT];        // 64 MB  - current activation
__device__ float g_h   [T_TOK * NEXP * RLORA]; // 4 MB  - masked gelu(z@A)
__device__ float g_mask[T_TOK * NEXP];         // 256 KB - top-2 mask (0/1)

// ---------------------------------------------------------------------------
// Fused SGEMM: C[M,1024] = A[M,KDIM] @ W[KDIM,1024]  (+ fused epilogues)
// BM=BN=128, BK=16, 256 threads, 8x8 per thread.
// MODE 0 (S): C = sigmoid(acc + bias) * X * td      (liquid gate+state)
// MODE 1 (Y): C = acc + bias + X                    (proj_out + residual)
// MODE 2 (P): C = acc                               (MoLE down-proj)
// ---------------------------------------------------------------------------
#define MODE_S 0
#define MODE_Y 1
#define MODE_P 2

template <int KDIM, int MODE>
__global__ __launch_bounds__(256)
void gemm128(const float* __restrict__ A, const float* __restrict__ W,
             const float* __restrict__ bias, const float* __restrict__ X,
             const float* __restrict__ td, float* __restrict__ C)
{
    const int N = 1024;
    __shared__ float As[16][132];   // transposed A tile (+pad, 16B-aligned rows)
    __shared__ float Ws[16][128];

    const int tid  = threadIdx.x;
    const int m0   = blockIdx.y * 128;
    const int n0   = blockIdx.x * 128;
    const int trow = tid >> 4;      // 0..15 -> rows trow*8..+7
    const int tcol = tid & 15;      // 0..15 -> cols tcol*8..+7

    float acc[8][8];
#pragma unroll
    for (int i = 0; i < 8; i++)
#pragma unroll
        for (int j = 0; j < 8; j++) acc[i][j] = 0.f;

    const int ar  = tid >> 2;       // 0..63
    const int ac4 = tid & 3;        // float4 column within the 16-wide A tile
    const int wr  = tid >> 5;       // 0..7
    const int wc4 = tid & 31;       // float4 column within the 128-wide W tile

    for (int k0 = 0; k0 < KDIM; k0 += 16) {
        // Load A tile (128 rows x 16 cols), store transposed
#pragma unroll
        for (int i = 0; i < 2; i++) {
            const int r = ar + i * 64;
            float4 v = *(const float4*)&A[(size_t)(m0 + r) * KDIM + k0 + ac4 * 4];
            As[ac4 * 4 + 0][r] = v.x;
            As[ac4 * 4 + 1][r] = v.y;
            As[ac4 * 4 + 2][r] = v.z;
            As[ac4 * 4 + 3][r] = v.w;
        }
        // Load W tile (16 rows x 128 cols)
#pragma unroll
        for (int i = 0; i < 2; i++) {
            const int r = wr + i * 8;
            float4 v = *(const float4*)&W[(size_t)(k0 + r) * N + n0 + wc4 * 4];
            *(float4*)&Ws[r][wc4 * 4] = v;
        }
        __syncthreads();

#pragma unroll
        for (int kk = 0; kk < 16; kk++) {
            float4 a0 = *(const float4*)&As[kk][trow * 8];
            float4 a1 = *(const float4*)&As[kk][trow * 8 + 4];
            float4 b0 = *(const float4*)&Ws[kk][tcol * 8];
            float4 b1 = *(const float4*)&Ws[kk][tcol * 8 + 4];
            float a[8] = {a0.x, a0.y, a0.z, a0.w, a1.x, a1.y, a1.z, a1.w};
            float b[8] = {b0.x, b0.y, b0.z, b0.w, b1.x, b1.y, b1.z, b1.w};
#pragma unroll
            for (int i = 0; i < 8; i++)
#pragma unroll
                for (int j = 0; j < 8; j++)
                    acc[i][j] = fmaf(a[i], b[j], acc[i][j]);
        }
        __syncthreads();
    }

    // Epilogue
#pragma unroll
    for (int i = 0; i < 8; i++) {
        const int m = m0 + trow * 8 + i;
        const int n = n0 + tcol * 8;
#pragma unroll
        for (int j = 0; j < 8; j++) {
            float v = acc[i][j];
            const int nn = n + j;
            if (MODE == MODE_S) {
                const float pre = v + bias[nn];
                const float sg  = 1.f / (1.f + expf(-pre));
                v = sg * X[(size_t)m * N + nn] * td[nn];
            } else if (MODE == MODE_Y) {
                v = v + bias[nn] + X[(size_t)m * N + nn];
            }
            C[(size_t)m * N + nn] = v;
        }
    }
}

// ---------------------------------------------------------------------------
// LayerNorm over D=1024; one block (256 threads) per token row.
// out = (y - mu) / sqrt(var + 1e-5) * g + beta
// ---------------------------------------------------------------------------
__global__ void ln_kernel(const float* __restrict__ Y, const float* __restrict__ g,
                          const float* __restrict__ b, float* __restrict__ out)
{
    __shared__ float sh[18];
    const int row = blockIdx.x;
    const int tid = threadIdx.x;
    const float* yr = Y + (size_t)row * 1024;

    float4 v = *(const float4*)&yr[tid * 4];
    float s = v.x + v.y + v.z + v.w;
#pragma unroll
    for (int o = 16; o; o >>= 1) s += __shfl_xor_sync(0xffffffffu, s, o);
    if ((tid & 31) == 0) sh[tid >> 5] = s;
    __syncthreads();
    if (tid == 0) {
        float t = 0.f;
        for (int i = 0; i < 8; i++) t += sh[i];
        sh[16] = t * (1.0f / 1024.0f);
    }
    __syncthreads();
    const float mu = sh[16];

    const float dx = v.x - mu, dy = v.y - mu, dz = v.z - mu, dw = v.w - mu;
    float q = dx * dx + dy * dy + dz * dz + dw * dw;
#pragma unroll
    for (int o = 16; o; o >>= 1) q += __shfl_xor_sync(0xffffffffu, q, o);
    if ((tid & 31) == 0) sh[8 + (tid >> 5)] = q;
    __syncthreads();
    if (tid == 0) {
        float t = 0.f;
        for (int i = 0; i < 8; i++) t += sh[8 + i];
        sh[17] = rsqrtf(t * (1.0f / 1024.0f) + 1e-5f);
    }
    __syncthreads();
    const float r = sh[17];

    float4 gv = *(const float4*)&g[tid * 4];
    float4 bv = *(const float4*)&b[tid * 4];
    float4 o4;
    o4.x = dx * r * gv.x + bv.x;
    o4.y = dy * r * gv.y + bv.y;
    o4.z = dz * r * gv.z + bv.z;
    o4.w = dw * r * gv.w + bv.w;
    *(float4*)&out[(size_t)row * 1024 + tid * 4] = o4;
}

// ---------------------------------------------------------------------------
// Gate: logits = z @ gate_W + gate_b -> softmax -> probs out; top-2 -> mask.
// One warp per token.
// ---------------------------------------------------------------------------
__global__ void gate_kernel(const float* __restrict__ Z, const float* __restrict__ gw,
                            const float* __restrict__ gb,
                            float* __restrict__ probs_out, float* __restrict__ mask_out)
{
    const int warp = (blockIdx.x * blockDim.x + threadIdx.x) >> 5;
    const int lane = threadIdx.x & 31;
    if (warp >= T_TOK) return;

    float a0 = 0.f, a1 = 0.f, a2 = 0.f, a3 = 0.f;
    const float* zr = Z + (size_t)warp * 1024;
    for (int d = lane; d < 1024; d += 32) {
        const float z = zr[d];
        float4 w = *(const float4*)&gw[d * 4];
        a0 = fmaf(z, w.x, a0); a1 = fmaf(z, w.y, a1);
        a2 = fmaf(z, w.z, a2); a3 = fmaf(z, w.w, a3);
    }
#pragma unroll
    for (int o = 16; o; o >>= 1) {
        a0 += __shfl_xor_sync(0xffffffffu, a0, o);
        a1 += __shfl_xor_sync(0xffffffffu, a1, o);
        a2 += __shfl_xor_sync(0xffffffffu, a2, o);
        a3 += __shfl_xor_sync(0xffffffffu, a3, o);
    }
    if (lane == 0) {
        float lg[4] = {a0 + gb[0], a1 + gb[1], a2 + gb[2], a3 + gb[3]};
        float mx = lg[0];
        for (int i = 1; i < 4; i++) mx = fmaxf(mx, lg[i]);
        float p[4], sum = 0.f;
        for (int i = 0; i < 4; i++) { p[i] = expf(lg[i] - mx); sum += p[i]; }
        const float inv = 1.f / sum;
        for (int i = 0; i < 4; i++) p[i] *= inv;

        // top-2 (strict >, ties keep lower index — matches jax top_k)
        int i1 = 0;
        for (int i = 1; i < 4; i++) if (p[i] > p[i1]) i1 = i;
        int i2 = -1;
        for (int i = 0; i < 4; i++)
            if (i != i1 && (i2 < 0 || p[i] > p[i2])) i2 = i;

        for (int i = 0; i < 4; i++) {
            probs_out[(size_t)warp * 4 + i] = p[i];
            mask_out[(size_t)warp * 4 + i]  = (i == i1 || i == i2) ? 1.f : 0.f;
        }
    }
}

// ---------------------------------------------------------------------------
// MoLE up-proj: H[T,64] = mask_expand * gelu( Z[T,1024] @ Aflat[1024,64] )
// where Aflat[k, e*16+r] = lora_A[e,k,r]. BM=128, N=64, BK=16.
// ---------------------------------------------------------------------------
__global__ __launch_bounds__(256)
void mole_h_kernel(const float* __restrict__ Z, const float* __restrict__ lora_A,
                   const float* __restrict__ mask, float* __restrict__ H)
{
    __shared__ float As[16][132];
    __shared__ float Ws[16][64];

    const int tid  = threadIdx.x;
    const int m0   = blockIdx.x * 128;
    const int trow = tid >> 4;   // 0..15 -> rows trow*8..+7
    const int tcol = tid & 15;   // 0..15 -> cols tcol*4..+3

    float acc[8][4];
#pragma unroll
    for (int i = 0; i < 8; i++)
#pragma unroll
        for (int j = 0; j < 4; j++) acc[i][j] = 0.f;

    const int ar  = tid >> 2;
    const int ac4 = tid & 3;

    for (int k0 = 0; k0 < 1024; k0 += 16) {
#pragma unroll
        for (int i = 0; i < 2; i++) {
            const int r = ar + i * 64;
            float4 v = *(const float4*)&Z[(size_t)(m0 + r) * 1024 + k0 + ac4 * 4];
            As[ac4 * 4 + 0][r] = v.x;
            As[ac4 * 4 + 1][r] = v.y;
            As[ac4 * 4 + 2][r] = v.z;
            As[ac4 * 4 + 3][r] = v.w;
        }
        // W tile: 16 (k) x 64 (n=e*16+r): 1024 floats, 4 per thread
#pragma unroll
        for (int i = 0; i < 4; i++) {
            const int lin = tid + 256 * i;
            const int k = lin >> 6;
            const int n = lin & 63;
            const int e = n >> 4;
            const int r = n & 15;
            Ws[k][n] = lora_A[(size_t)e * (1024 * 16) + (size_t)(k0 + k) * 16 + r];
        }
        __syncthreads();

#pragma unroll
        for (int kk = 0; kk < 16; kk++) {
            float4 a0 = *(const float4*)&As[kk][trow * 8];
            float4 a1 = *(const float4*)&As[kk][trow * 8 + 4];
            float4 b0 = *(const float4*)&Ws[kk][tcol * 4];
            float a[8] = {a0.x, a0.y, a0.z, a0.w, a1.x, a1.y, a1.z, a1.w};
            float b[4] = {b0.x, b0.y, b0.z, b0.w};
#pragma unroll
            for (int i = 0; i < 8; i++)
#pragma unroll
                for (int j = 0; j < 4; j++)
                    acc[i][j] = fmaf(a[i], b[j], acc[i][j]);
        }
        __syncthreads();
    }

#pragma unroll
    for (int i = 0; i < 8; i++) {
        const int m = m0 + trow * 8 + i;
#pragma unroll
        for (int j = 0; j < 4; j++) {
            const int n = tcol * 4 + j;
            const float x  = acc[i][j];
            const float hv = 0.5f * x * (1.f + erff(x * 0.70710678118654752f));
            H[(size_t)m * 64 + n] = hv * mask[(size_t)m * 4 + (n >> 4)];
        }
    }
}

// ---------------------------------------------------------------------------
// Driver
// ---------------------------------------------------------------------------
static void run_stack(const float* x_in, const float* Wi, const float* bi,
                      const float* td, const float* Wo, const float* bo,
                      const float* g, const float* beta,
                      float* pS, float* pY, float* pX, float* final_out)
{
    const dim3 ggrid(8, 128), gblk(256);
    const float* cur = x_in;
    for (int l = 0; l < NLAYER; l++) {
        const size_t wo = (size_t)l * DLAT * DLAT;
        const size_t vo = (size_t)l * DLAT;
        gemm128<1024, MODE_S><<<ggrid, gblk>>>(cur, Wi + wo, bi + vo, cur, td + vo, pS);
        gemm128<1024, MODE_Y><<<ggrid, gblk>>>(pS, Wo + wo, bo + vo, cur, nullptr, pY);
        float* lnout = (l == NLAYER - 1) ? final_out : pX;
        ln_kernel<<<T_TOK, 256>>>(pY, g + vo, beta + vo, lnout);
        cur = lnout;
    }
}

extern "C" void kernel_launch(void* const* d_in, const int* in_sizes, int n_in,
                              void* d_out, int out_size)
{
    (void)in_sizes; (void)n_in; (void)out_size;

    const float* xc      = (const float*)d_in[0];
    const float* xt      = (const float*)d_in[1];
    const float* enc_Wi  = (const float*)d_in[2];
    const float* enc_bi  = (const float*)d_in[3];
    const float* enc_td  = (const float*)d_in[4];
    const float* enc_Wo  = (const float*)d_in[5];
    const float* enc_bo  = (const float*)d_in[6];
    const float* enc_g   = (const float*)d_in[7];
    const float* enc_be  = (const float*)d_in[8];
    const float* tgt_Wi  = (const float*)d_in[9];
    const float* tgt_bi  = (const float*)d_in[10];
    const float* tgt_td  = (const float*)d_in[11];
    const float* tgt_Wo  = (const float*)d_in[12];
    const float* tgt_bo  = (const float*)d_in[13];
    const float* tgt_g   = (const float*)d_in[14];
    const float* tgt_be  = (const float*)d_in[15];
    const float* gate_W  = (const float*)d_in[16];
    const float* gate_b  = (const float*)d_in[17];
    const float* lora_A  = (const float*)d_in[18];
    const float* lora_B  = (const float*)d_in[19];

    float* out = (float*)d_out;
    float* out_pred  = out;                                      // [T, D]
    float* out_probs = out + (size_t)T_TOK * DLAT;               // [T, E]
    float* out_ztgt  = out + (size_t)T_TOK * DLAT + (size_t)T_TOK * NEXP; // [T, D]

    static float *pS = nullptr, *pY = nullptr, *pX = nullptr, *pH = nullptr, *pM = nullptr;
    if (!pS) {
        cudaGetSymbolAddress((void**)&pS, g_bufS);
        cudaGetSymbolAddress((void**)&pY, g_bufY);
        cudaGetSymbolAddress((void**)&pX, g_bufX);
        cudaGetSymbolAddress((void**)&pH, g_h);
        cudaGetSymbolAddress((void**)&pM, g_mask);
    }

    // 1) encoder stack -> z_context in pX
    run_stack(xc, enc_Wi, enc_bi, enc_td, enc_Wo, enc_bo, enc_g, enc_be,
              pS, pY, pX, pX);

    // 2) MoLE on z_context
    gate_kernel<<<T_TOK * 32 / 256, 256>>>(pX, gate_W, gate_b, out_probs, pM);
    mole_h_kernel<<<T_TOK / 128, 256>>>(pX, lora_A, pM, pH);
    gemm128<64, MODE_P><<<dim3(8, 128), 256>>>(pH, lora_B, nullptr, nullptr, nullptr, out_pred);

    // 3) target stack -> z_target directly into the output region
    run_stack(xt, tgt_Wi, tgt_bi, tgt_td, tgt_Wo, tgt_bo, tgt_g, tgt_be,
              pS, pY, pX, out_ztgt);
}

// round 3
// speedup vs baseline: 1.8672x; 1.8672x over previous
#include <cuda_runtime.h>
#include <cuda_bf16.h>
#include <math.h>
#include <stdint.h>

// ---------------------------------------------------------------------------
// Problem constants
// ---------------------------------------------------------------------------
#define T_TOK 16384
#define DLAT  1024
#define NEXP  4
#define RLORA 16
#define NLAYER 3

// GEMM tiling
#define BM 128
#define BN 128
#define BK 32
#define KITERS (DLAT / BK)       // 32
#define PITCH_B 80               // bytes per smem row (40 bf16)
#define MAT_BYTES (128 * PITCH_B)        // 10240
#define STAGE_BYTES (4 * MAT_BYTES)      // 40960: Ah | Al | Wh | Wl
#define NSTAGE 3
#define SMEM_TOTAL (NSTAGE * STAGE_BYTES)  // 122880

#define MODE_S 0
#define MODE_Y 1

// ---------------------------------------------------------------------------
// Scratch
// ---------------------------------------------------------------------------
__device__ __nv_bfloat16 g_acth[2 * T_TOK * DLAT];   // slot0 = x, slot1 = s
__device__ __nv_bfloat16 g_actl[2 * T_TOK * DLAT];
__device__ __nv_bfloat16 g_WhT[12 * DLAT * DLAT];    // [slot][N][K]
__device__ __nv_bfloat16 g_WlT[12 * DLAT * DLAT];
__device__ float g_bufX[T_TOK * DLAT];
__device__ float g_bufY[T_TOK * DLAT];
__device__ float g_h[T_TOK * NEXP * RLORA];
__device__ float g_mask[T_TOK * NEXP];

// ---------------------------------------------------------------------------
// PTX helpers (all base sm_80-era features; no arch-specific 'a' required)
// ---------------------------------------------------------------------------
__device__ __forceinline__ uint32_t smem_to_u32(const void* p) {
    uint32_t a;
    asm("{ .reg .u64 t; cvta.to.shared.u64 t, %1; cvt.u32.u64 %0, t; }" : "=r"(a) : "l"(p));
    return a;
}

__device__ __forceinline__ void cp16(uint32_t dst, const void* src) {
    asm volatile("cp.async.cg.shared.global [%0], [%1], 16;" :: "r"(dst), "l"(src));
}

#define CP_COMMIT() asm volatile("cp.async.commit_group;" ::: "memory")
#define CP_WAIT1()  asm volatile("cp.async.wait_group 1;" ::: "memory")

#define LDSM4(r0, r1, r2, r3, addr) \
    asm volatile("ldmatrix.sync.aligned.m8n8.x4.shared.b16 {%0,%1,%2,%3}, [%4];" \
                 : "=r"(r0), "=r"(r1), "=r"(r2), "=r"(r3) : "r"(addr))

__device__ __forceinline__ void hmma(float* d, const uint32_t* a, const uint32_t* b) {
    asm volatile(
        "mma.sync.aligned.m16n8k16.row.col.f32.bf16.bf16.f32 "
        "{%0,%1,%2,%3}, {%4,%5,%6,%7}, {%8,%9}, {%0,%1,%2,%3};"
        : "+f"(d[0]), "+f"(d[1]), "+f"(d[2]), "+f"(d[3])
        : "r"(a[0]), "r"(a[1]), "r"(a[2]), "r"(a[3]), "r"(b[0]), "r"(b[1]));
}

// ---------------------------------------------------------------------------
// bf16-split HMMA GEMM: C[M,1024] = A[M,1024] @ W^T  (W stored [N][K])
// acc = Ah*Wh + Ah*Wl + Al*Wh   (Markidis 3-term split)
// MODE_S: s = sigmoid(acc + bias) * X * td -> Ch/Cl bf16 hi/lo
// MODE_Y: y = acc + bias + X              -> Cf fp32
// ---------------------------------------------------------------------------
template <int MODE>
__global__ __launch_bounds__(256)
void hgemm(const __nv_bfloat16* __restrict__ Ah, const __nv_bfloat16* __restrict__ Al,
           const __nv_bfloat16* __restrict__ Wh, const __nv_bfloat16* __restrict__ Wl,
           const float* __restrict__ bias, const float* __restrict__ X,
           const float* __restrict__ td, float* __restrict__ Cf,
           __nv_bfloat16* __restrict__ Ch, __nv_bfloat16* __restrict__ Cl)
{
    extern __shared__ char smem[];
    const uint32_t sb = smem_to_u32(smem);
    const int tid = threadIdx.x;
    const int wid = tid >> 5;
    const int lane = tid & 31;
    const int wm = wid >> 2;        // 0..1 -> rows wm*64..+63
    const int wn = wid & 3;         // 0..3 -> cols wn*32..+31
    const int m0 = blockIdx.y * BM;
    const int n0 = blockIdx.x * BN;

    // cp.async mapping: 256 threads, each loads 2x16B per matrix per stage
    const int lrow = tid >> 1;              // 0..127
    const int lch  = tid & 1;               // half-row (32B)
    const __nv_bfloat16* sAh = Ah + (size_t)(m0 + lrow) * DLAT + lch * 16;
    const __nv_bfloat16* sAl = Al + (size_t)(m0 + lrow) * DLAT + lch * 16;
    const __nv_bfloat16* sWh = Wh + (size_t)(n0 + lrow) * DLAT + lch * 16;
    const __nv_bfloat16* sWl = Wl + (size_t)(n0 + lrow) * DLAT + lch * 16;
    const uint32_t dbase = sb + lrow * PITCH_B + lch * 32;

    // ldmatrix lane offsets
    const int a_row = (lane & 7) + ((lane >> 3) & 1) * 8;
    const int a_k   = ((lane >> 4) & 1) * 8;
    const int b_row = (lane & 7) + ((lane >> 4) & 1) * 8;
    const int b_k   = ((lane >> 3) & 1) * 8;

    float acc[4][4][4];
#pragma unroll
    for (int i = 0; i < 4; i++)
#pragma unroll
        for (int j = 0; j < 4; j++)
#pragma unroll
            for (int q = 0; q < 4; q++) acc[i][j][q] = 0.f;

    // prologue: stages 0,1
#pragma unroll
    for (int s = 0; s < 2; s++) {
        const int k0 = s * BK;
        const uint32_t d = dbase + s * STAGE_BYTES;
        cp16(d,                  sAh + k0); cp16(d + 16,                  sAh + k0 + 8);
        cp16(d + MAT_BYTES,      sAl + k0); cp16(d + MAT_BYTES + 16,      sAl + k0 + 8);
        cp16(d + 2 * MAT_BYTES,  sWh + k0); cp16(d + 2 * MAT_BYTES + 16,  sWh + k0 + 8);
        cp16(d + 3 * MAT_BYTES,  sWl + k0); cp16(d + 3 * MAT_BYTES + 16,  sWl + k0 + 8);
        CP_COMMIT();
    }

    for (int it = 0; it < KITERS; it++) {
        CP_WAIT1();
        __syncthreads();
        const int pf = it + 2;
        if (pf < KITERS) {
            const int k0 = pf * BK;
            const uint32_t d = dbase + (pf % NSTAGE) * STAGE_BYTES;
            cp16(d,                  sAh + k0); cp16(d + 16,                  sAh + k0 + 8);
            cp16(d + MAT_BYTES,      sAl + k0); cp16(d + MAT_BYTES + 16,      sAl + k0 + 8);
            cp16(d + 2 * MAT_BYTES,  sWh + k0); cp16(d + 2 * MAT_BYTES + 16,  sWh + k0 + 8);
            cp16(d + 3 * MAT_BYTES,  sWl + k0); cp16(d + 3 * MAT_BYTES + 16,  sWl + k0 + 8);
        }
        CP_COMMIT();

        const uint32_t st = sb + (it % NSTAGE) * STAGE_BYTES;
#pragma unroll
        for (int ko = 0; ko < BK; ko += 16) {
            uint32_t ah[4][4], al[4][4], bh[4][2], bl[4][2];
#pragma unroll
            for (int mi = 0; mi < 4; mi++) {
                const uint32_t ra = st + (uint32_t)(wm * 64 + mi * 16 + a_row) * PITCH_B
                                       + (uint32_t)(ko + a_k) * 2;
                LDSM4(ah[mi][0], ah[mi][1], ah[mi][2], ah[mi][3], ra);
                LDSM4(al[mi][0], al[mi][1], al[mi][2], al[mi][3], ra + MAT_BYTES);
            }
#pragma unroll
            for (int np = 0; np < 2; np++) {
                const uint32_t rb = st + 2 * MAT_BYTES
                                       + (uint32_t)(wn * 32 + np * 16 + b_row) * PITCH_B
                                       + (uint32_t)(ko + b_k) * 2;
                uint32_t t0, t1, t2, t3;
                LDSM4(t0, t1, t2, t3, rb);
                bh[2 * np][0] = t0; bh[2 * np][1] = t1;
                bh[2 * np + 1][0] = t2; bh[2 * np + 1][1] = t3;
                LDSM4(t0, t1, t2, t3, rb + MAT_BYTES);
                bl[2 * np][0] = t0; bl[2 * np][1] = t1;
                bl[2 * np + 1][0] = t2; bl[2 * np + 1][1] = t3;
            }
#pragma unroll
            for (int mi = 0; mi < 4; mi++)
#pragma unroll
                for (int ni = 0; ni < 4; ni++) {
                    hmma(acc[mi][ni], ah[mi], bh[ni]);
                    hmma(acc[mi][ni], ah[mi], bl[ni]);
                    hmma(acc[mi][ni], al[mi], bh[ni]);
                }
        }
    }

    // ---------------- epilogue (direct from registers) ----------------
    const int qr = lane >> 2;
    const int qc = (lane & 3) * 2;
#pragma unroll
    for (int mi = 0; mi < 4; mi++) {
#pragma unroll
        for (int ni = 0; ni < 4; ni++) {
            const int r = m0 + wm * 64 + mi * 16 + qr;
            const int c = n0 + wn * 32 + ni * 8 + qc;
            const float* d = acc[mi][ni];
#pragma unroll
            for (int h = 0; h < 2; h++) {
                const int rr = r + h * 8;
                const float v0 = d[2 * h], v1 = d[2 * h + 1];
                const float2 xv = *(const float2*)&X[(size_t)rr * DLAT + c];
                const float2 bv = *(const float2*)&bias[c];
                if (MODE == MODE_S) {
                    const float2 tv = *(const float2*)&td[c];
                    const float s0 = (1.f / (1.f + expf(-(v0 + bv.x)))) * xv.x * tv.x;
                    const float s1 = (1.f / (1.f + expf(-(v1 + bv.y)))) * xv.y * tv.y;
                    const __nv_bfloat16 h0 = __float2bfloat16(s0);
                    const __nv_bfloat16 h1 = __float2bfloat16(s1);
                    const __nv_bfloat16 l0 = __float2bfloat16(s0 - __bfloat162float(h0));
                    const __nv_bfloat16 l1 = __float2bfloat16(s1 - __bfloat162float(h1));
                    *(__nv_bfloat162*)&Ch[(size_t)rr * DLAT + c] = __nv_bfloat162(h0, h1);
                    *(__nv_bfloat162*)&Cl[(size_t)rr * DLAT + c] = __nv_bfloat162(l0, l1);
                } else {
                    float2 o;
                    o.x = v0 + bv.x + xv.x;
                    o.y = v1 + bv.y + xv.y;
                    *(float2*)&Cf[(size_t)rr * DLAT + c] = o;
                }
            }
        }
    }
}

// ---------------------------------------------------------------------------
// Weight transpose + bf16 split: W[l][K][N] fp32 -> WT[slot][N][K] hi/lo bf16
// ---------------------------------------------------------------------------
__global__ void wsplit_kernel(const float* __restrict__ W, int slot_base, int slot_stride,
                              __nv_bfloat16* __restrict__ WhT, __nv_bfloat16* __restrict__ WlT)
{
    __shared__ float t[32][33];
    const int l = blockIdx.z;
    const float* Wl = W + (size_t)l * DLAT * DLAT;
    const int bx = blockIdx.x * 32;   // n
    const int by = blockIdx.y * 32;   // k
    const int tx = threadIdx.x, ty = threadIdx.y;
#pragma unroll
    for (int i = 0; i < 32; i += 8)
        t[ty + i][tx] = Wl[(size_t)(by + ty + i) * DLAT + bx + tx];
    __syncthreads();
    const size_t slot = (size_t)(slot_base + l * slot_stride) * DLAT * DLAT;
#pragma unroll
    for (int i = 0; i < 32; i += 8) {
        const float v = t[tx][ty + i];   // = W[by+tx][bx+ty+i]
        const __nv_bfloat16 h = __float2bfloat16(v);
        const size_t o = slot + (size_t)(bx + ty + i) * DLAT + by + tx;
        WhT[o] = h;
        WlT[o] = __float2bfloat16(v - __bfloat162float(h));
    }
}

// ---------------------------------------------------------------------------
// Activation split: fp32 -> bf16 hi/lo
// ---------------------------------------------------------------------------
__global__ void asplit_kernel(const float* __restrict__ x,
                              __nv_bfloat16* __restrict__ oh, __nv_bfloat16* __restrict__ ol)
{
    const int i = blockIdx.x * blockDim.x + threadIdx.x;
    const float4 v = ((const float4*)x)[i];
    __nv_bfloat16 h0 = __float2bfloat16(v.x), h1 = __float2bfloat16(v.y);
    __nv_bfloat16 h2 = __float2bfloat16(v.z), h3 = __float2bfloat16(v.w);
    __nv_bfloat162* oh2 = (__nv_bfloat162*)oh;
    __nv_bfloat162* ol2 = (__nv_bfloat162*)ol;
    oh2[2 * i]     = __nv_bfloat162(h0, h1);
    oh2[2 * i + 1] = __nv_bfloat162(h2, h3);
    ol2[2 * i]     = __nv_bfloat162(__float2bfloat16(v.x - __bfloat162float(h0)),
                                    __float2bfloat16(v.y - __bfloat162float(h1)));
    ol2[2 * i + 1] = __nv_bfloat162(__float2bfloat16(v.z - __bfloat162float(h2)),
                                    __float2bfloat16(v.w - __bfloat162float(h3)));
}

// ---------------------------------------------------------------------------
// LayerNorm (+ optional bf16 hi/lo split of the output)
// ---------------------------------------------------------------------------
__global__ void ln_kernel(const float* __restrict__ Y, const float* __restrict__ g,
                          const float* __restrict__ b, float* __restrict__ out,
                          __nv_bfloat16* __restrict__ oh, __nv_bfloat16* __restrict__ ol)
{
    __shared__ float sh[18];
    const int row = blockIdx.x;
    const int tid = threadIdx.x;
    const float* yr = Y + (size_t)row * DLAT;

    float4 v = *(const float4*)&yr[tid * 4];
    float s = v.x + v.y + v.z + v.w;
#pragma unroll
    for (int o = 16; o; o >>= 1) s += __shfl_xor_sync(0xffffffffu, s, o);
    if ((tid & 31) == 0) sh[tid >> 5] = s;
    __syncthreads();
    if (tid == 0) {
        float t = 0.f;
        for (int i = 0; i < 8; i++) t += sh[i];
        sh[16] = t * (1.0f / 1024.0f);
    }
    __syncthreads();
    const float mu = sh[16];
    const float dx = v.x - mu, dy = v.y - mu, dz = v.z - mu, dw = v.w - mu;
    float q = dx * dx + dy * dy + dz * dz + dw * dw;
#pragma unroll
    for (int o = 16; o; o >>= 1) q += __shfl_xor_sync(0xffffffffu, q, o);
    if ((tid & 31) == 0) sh[8 + (tid >> 5)] = q;
    __syncthreads();
    if (tid == 0) {
        float t = 0.f;
        for (int i = 0; i < 8; i++) t += sh[8 + i];
        sh[17] = rsqrtf(t * (1.0f / 1024.0f) + 1e-5f);
    }
    __syncthreads();
    const float r = sh[17];

    float4 gv = *(const float4*)&g[tid * 4];
    float4 bv = *(const float4*)&b[tid * 4];
    float4 o4;
    o4.x = dx * r * gv.x + bv.x;
    o4.y = dy * r * gv.y + bv.y;
    o4.z = dz * r * gv.z + bv.z;
    o4.w = dw * r * gv.w + bv.w;
    *(float4*)&out[(size_t)row * DLAT + tid * 4] = o4;

    if (oh) {
        const size_t o = (size_t)row * DLAT + tid * 4;
        __nv_bfloat16 h0 = __float2bfloat16(o4.x), h1 = __float2bfloat16(o4.y);
        __nv_bfloat16 h2 = __float2bfloat16(o4.z), h3 = __float2bfloat16(o4.w);
        *(__nv_bfloat162*)&oh[o]     = __nv_bfloat162(h0, h1);
        *(__nv_bfloat162*)&oh[o + 2] = __nv_bfloat162(h2, h3);
        *(__nv_bfloat162*)&ol[o]     = __nv_bfloat162(__float2bfloat16(o4.x - __bfloat162float(h0)),
                                                      __float2bfloat16(o4.y - __bfloat162float(h1)));
        *(__nv_bfloat162*)&ol[o + 2] = __nv_bfloat162(__float2bfloat16(o4.z - __bfloat162float(h2)),
                                                      __float2bfloat16(o4.w - __bfloat162float(h3)));
    }
}

// ---------------------------------------------------------------------------
// Gate: softmax + top-2 mask (one warp per token)
// ---------------------------------------------------------------------------
__global__ void gate_kernel(const float* __restrict__ Z, const float* __restrict__ gw,
                            const float* __restrict__ gb,
                            float* __restrict__ probs_out, float* __restrict__ mask_out)
{
    const int warp = (blockIdx.x * blockDim.x + threadIdx.x) >> 5;
    const int lane = threadIdx.x & 31;
    if (warp >= T_TOK) return;

    float a0 = 0.f, a1 = 0.f, a2 = 0.f, a3 = 0.f;
    const float* zr = Z + (size_t)warp * DLAT;
    for (int d = lane; d < DLAT; d += 32) {
        const float z = zr[d];
        float4 w = *(const float4*)&gw[d * 4];
        a0 = fmaf(z, w.x, a0); a1 = fmaf(z, w.y, a1);
        a2 = fmaf(z, w.z, a2); a3 = fmaf(z, w.w, a3);
    }
#pragma unroll
    for (int o = 16; o; o >>= 1) {
        a0 += __shfl_xor_sync(0xffffffffu, a0, o);
        a1 += __shfl_xor_sync(0xffffffffu, a1, o);
        a2 += __shfl_xor_sync(0xffffffffu, a2, o);
        a3 += __shfl_xor_sync(0xffffffffu, a3, o);
    }
    if (lane == 0) {
        float lg[4] = {a0 + gb[0], a1 + gb[1], a2 + gb[2], a3 + gb[3]};
        float mx = lg[0];
        for (int i = 1; i < 4; i++) mx = fmaxf(mx, lg[i]);
        float p[4], sum = 0.f;
        for (int i = 0; i < 4; i++) { p[i] = expf(lg[i] - mx); sum += p[i]; }
        const float inv = 1.f / sum;
        for (int i = 0; i < 4; i++) p[i] *= inv;
        int i1 = 0;
        for (int i = 1; i < 4; i++) if (p[i] > p[i1]) i1 = i;
        int i2 = -1;
        for (int i = 0; i < 4; i++)
            if (i != i1 && (i2 < 0 || p[i] > p[i2])) i2 = i;
        for (int i = 0; i < 4; i++) {
            probs_out[(size_t)warp * 4 + i] = p[i];
            mask_out[(size_t)warp * 4 + i] = (i == i1 || i == i2) ? 1.f : 0.f;
        }
    }
}

// ---------------------------------------------------------------------------
// MoLE up-proj (SIMT): H = mask * gelu(Z @ Aflat), N=64
// ---------------------------------------------------------------------------
__global__ __launch_bounds__(256)
void mole_h_kernel(const float* __restrict__ Z, const float* __restrict__ lora_A,
                   const float* __restrict__ mask, float* __restrict__ H)
{
    __shared__ float As[16][132];
    __shared__ float Ws[16][64];
    const int tid = threadIdx.x;
    const int m0 = blockIdx.x * 128;
    const int trow = tid >> 4;
    const int tcol = tid & 15;

    float acc[8][4];
#pragma unroll
    for (int i = 0; i < 8; i++)
#pragma unroll
        for (int j = 0; j < 4; j++) acc[i][j] = 0.f;

    const int ar = tid >> 2;
    const int ac4 = tid & 3;

    for (int k0 = 0; k0 < 1024; k0 += 16) {
#pragma unroll
        for (int i = 0; i < 2; i++) {
            const int r = ar + i * 64;
            float4 v = *(const float4*)&Z[(size_t)(m0 + r) * 1024 + k0 + ac4 * 4];
            As[ac4 * 4 + 0][r] = v.x; As[ac4 * 4 + 1][r] = v.y;
            As[ac4 * 4 + 2][r] = v.z; As[ac4 * 4 + 3][r] = v.w;
        }
#pragma unroll
        for (int i = 0; i < 4; i++) {
            const int lin = tid + 256 * i;
            const int k = lin >> 6, n = lin & 63;
            Ws[k][n] = lora_A[(size_t)(n >> 4) * (1024 * 16) + (size_t)(k0 + k) * 16 + (n & 15)];
        }
        __syncthreads();
#pragma unroll
        for (int kk = 0; kk < 16; kk++) {
            float4 a0 = *(const float4*)&As[kk][trow * 8];
            float4 a1 = *(const float4*)&As[kk][trow * 8 + 4];
            float4 b0 = *(const float4*)&Ws[kk][tcol * 4];
            float a[8] = {a0.x, a0.y, a0.z, a0.w, a1.x, a1.y, a1.z, a1.w};
            float b[4] = {b0.x, b0.y, b0.z, b0.w};
#pragma unroll
            for (int i = 0; i < 8; i++)
#pragma unroll
                for (int j = 0; j < 4; j++)
                    acc[i][j] = fmaf(a[i], b[j], acc[i][j]);
        }
        __syncthreads();
    }
#pragma unroll
    for (int i = 0; i < 8; i++) {
        const int m = m0 + trow * 8 + i;
#pragma unroll
        for (int j = 0; j < 4; j++) {
            const int n = tcol * 4 + j;
            const float x = acc[i][j];
            const float hv = 0.5f * x * (1.f + erff(x * 0.70710678118654752f));
            H[(size_t)m * 64 + n] = hv * mask[(size_t)m * 4 + (n >> 4)];
        }
    }
}

// ---------------------------------------------------------------------------
// MoLE down-proj (SIMT): C[T,1024] = H[T,64] @ loraB[64,1024]
// ---------------------------------------------------------------------------
__global__ __launch_bounds__(256)
void mole_p_kernel(const float* __restrict__ A, const float* __restrict__ W,
                   float* __restrict__ C)
{
    const int N = 1024;
    __shared__ float As[16][132];
    __shared__ float Ws[16][128];
    const int tid = threadIdx.x;
    const int m0 = blockIdx.y * 128;
    const int n0 = blockIdx.x * 128;
    const int trow = tid >> 4;
    const int tcol = tid & 15;

    float acc[8][8];
#pragma unroll
    for (int i = 0; i < 8; i++)
#pragma unroll
        for (int j = 0; j < 8; j++) acc[i][j] = 0.f;

    const int ar = tid >> 2;
    const int ac4 = tid & 3;
    const int wr = tid >> 5;
    const int wc4 = tid & 31;

    for (int k0 = 0; k0 < 64; k0 += 16) {
#pragma unroll
        for (int i = 0; i < 2; i++) {
            const int r = ar + i * 64;
            float4 v = *(const float4*)&A[(size_t)(m0 + r) * 64 + k0 + ac4 * 4];
            As[ac4 * 4 + 0][r] = v.x; As[ac4 * 4 + 1][r] = v.y;
            As[ac4 * 4 + 2][r] = v.z; As[ac4 * 4 + 3][r] = v.w;
        }
#pragma unroll
        for (int i = 0; i < 2; i++) {
            const int r = wr + i * 8;
            float4 v = *(const float4*)&W[(size_t)(k0 + r) * N + n0 + wc4 * 4];
            *(float4*)&Ws[r][wc4 * 4] = v;
        }
        __syncthreads();
#pragma unroll
        for (int kk = 0; kk < 16; kk++) {
            float4 a0 = *(const float4*)&As[kk][trow * 8];
            float4 a1 = *(const float4*)&As[kk][trow * 8 + 4];
            float4 b0 = *(const float4*)&Ws[kk][tcol * 8];
            float4 b1 = *(const float4*)&Ws[kk][tcol * 8 + 4];
            float a[8] = {a0.x, a0.y, a0.z, a0.w, a1.x, a1.y, a1.z, a1.w};
            float b[8] = {b0.x, b0.y, b0.z, b0.w, b1.x, b1.y, b1.z, b1.w};
#pragma unroll
            for (int i = 0; i < 8; i++)
#pragma unroll
                for (int j = 0; j < 8; j++)
                    acc[i][j] = fmaf(a[i], b[j], acc[i][j]);
        }
        __syncthreads();
    }
#pragma unroll
    for (int i = 0; i < 8; i++) {
        const int m = m0 + trow * 8 + i;
#pragma unroll
        for (int j = 0; j < 8; j++)
            C[(size_t)m * N + tcol * 8 + n0 + j] = acc[i][j];
    }
}

// ---------------------------------------------------------------------------
// Host driver
// ---------------------------------------------------------------------------
extern "C" void kernel_launch(void* const* d_in, const int* in_sizes, int n_in,
                              void* d_out, int out_size)
{
    (void)in_sizes; (void)n_in; (void)out_size;

    const float* xc     = (const float*)d_in[0];
    const float* xt     = (const float*)d_in[1];
    const float* enc_Wi = (const float*)d_in[2];
    const float* enc_bi = (const float*)d_in[3];
    const float* enc_td = (const float*)d_in[4];
    const float* enc_Wo = (const float*)d_in[5];
    const float* enc_bo = (const float*)d_in[6];
    const float* enc_g  = (const float*)d_in[7];
    const float* enc_be = (const float*)d_in[8];
    const float* tgt_Wi = (const float*)d_in[9];
    const float* tgt_bi = (const float*)d_in[10];
    const float* tgt_td = (const float*)d_in[11];
    const float* tgt_Wo = (const float*)d_in[12];
    const float* tgt_bo = (const float*)d_in[13];
    const float* tgt_g  = (const float*)d_in[14];
    const float* tgt_be = (const float*)d_in[15];
    const float* gate_W = (const float*)d_in[16];
    const float* gate_b = (const float*)d_in[17];
    const float* lora_A = (const float*)d_in[18];
    const float* lora_B = (const float*)d_in[19];

    float* out = (float*)d_out;
    float* out_pred  = out;
    float* out_probs = out + (size_t)T_TOK * DLAT;
    float* out_ztgt  = out + (size_t)T_TOK * DLAT + (size_t)T_TOK * NEXP;

    static __nv_bfloat16 *pAh = nullptr, *pAl, *pWh, *pWl;
    static float *pX, *pY, *pH, *pM;
    if (!pAh) {
        cudaGetSymbolAddress((void**)&pAh, g_acth);
        cudaGetSymbolAddress((void**)&pAl, g_actl);
        cudaGetSymbolAddress((void**)&pWh, g_WhT);
        cudaGetSymbolAddress((void**)&pWl, g_WlT);
        cudaGetSymbolAddress((void**)&pX, g_bufX);
        cudaGetSymbolAddress((void**)&pY, g_bufY);
        cudaGetSymbolAddress((void**)&pH, g_h);
        cudaGetSymbolAddress((void**)&pM, g_mask);
        cudaFuncSetAttribute(hgemm<MODE_S>, cudaFuncAttributeMaxDynamicSharedMemorySize, SMEM_TOTAL);
        cudaFuncSetAttribute(hgemm<MODE_Y>, cudaFuncAttributeMaxDynamicSharedMemorySize, SMEM_TOTAL);
    }

    // weight transpose+split: slots enc: Wi->0,2,4 Wo->1,3,5; tgt: Wi->6,8,10 Wo->7,9,11
    const dim3 wgrid(32, 32, 3), wblk(32, 8);
    wsplit_kernel<<<wgrid, wblk>>>(enc_Wi, 0, 2, pWh, pWl);
    wsplit_kernel<<<wgrid, wblk>>>(enc_Wo, 1, 2, pWh, pWl);
    wsplit_kernel<<<wgrid, wblk>>>(tgt_Wi, 6, 2, pWh, pWl);
    wsplit_kernel<<<wgrid, wblk>>>(tgt_Wo, 7, 2, pWh, pWl);

    const dim3 ggrid(DLAT / BN, T_TOK / BM);   // (8, 128)
    const size_t slot1 = (size_t)T_TOK * DLAT;
    const size_t wsz = (size_t)DLAT * DLAT;

    for (int stack = 0; stack < 2; stack++) {
        const float* x_in = stack == 0 ? xc : xt;
        const float* p_bi = stack == 0 ? enc_bi : tgt_bi;
        const float* p_td = stack == 0 ? enc_td : tgt_td;
        const float* p_bo = stack == 0 ? enc_bo : tgt_bo;
        const float* p_g  = stack == 0 ? enc_g  : tgt_g;
        const float* p_be = stack == 0 ? enc_be : tgt_be;
        float* final_out = stack == 0 ? pX : out_ztgt;

        asplit_kernel<<<(T_TOK * DLAT / 4) / 256, 256>>>(x_in, pAh, pAl);

        const float* cur = x_in;
        for (int l = 0; l < NLAYER; l++) {
            const size_t vo = (size_t)l * DLAT;
            const int wi_slot = stack * 6 + l * 2;
            // gemm1: s = sigmoid(x@Wi + bi) * x * td  -> act slot1 (hi/lo)
            hgemm<MODE_S><<<ggrid, 256, SMEM_TOTAL>>>(
                pAh, pAl, pWh + (size_t)wi_slot * wsz, pWl + (size_t)wi_slot * wsz,
                p_bi + vo, cur, p_td + vo,
                nullptr, pAh + slot1, pAl + slot1);
            // gemm2: y = s@Wo + bo + x -> g_bufY
            hgemm<MODE_Y><<<ggrid, 256, SMEM_TOTAL>>>(
                pAh + slot1, pAl + slot1,
                pWh + (size_t)(wi_slot + 1) * wsz, pWl + (size_t)(wi_slot + 1) * wsz,
                p_bo + vo, cur, nullptr,
                pY, nullptr, nullptr);
            float* lnout = (l == NLAYER - 1) ? final_out : pX;
            const bool need_bf16 = (l < NLAYER - 1);
            ln_kernel<<<T_TOK, 256>>>(pY, p_g + vo, p_be + vo, lnout,
                                      need_bf16 ? pAh : nullptr,
                                      need_bf16 ? pAl : nullptr);
            cur = lnout;
        }

        if (stack == 0) {
            gate_kernel<<<T_TOK * 32 / 256, 256>>>(pX, gate_W, gate_b, out_probs, pM);
            mole_h_kernel<<<T_TOK / 128, 256>>>(pX, lora_A, pM, pH);
            mole_p_kernel<<<dim3(8, 128), 256>>>(pH, lora_B, out_pred);
        }
    }
}